// round 12
// baseline (speedup 1.0000x reference)
#include <cuda_runtime.h>
#include <cstdint>

#define TABLE_N  262144
#define NTHREADS 256
#define PPT      8                     // points per thread per tile
#define CTA_PTS  (NTHREADS * PPT)      // 2048
#define NSM      148
#define CTAS_PER_SM 8

// Packed (weight, bias) table — static __device__ scratch, rebuilt every call.
__device__ __align__(16) float2 g_wb[TABLE_N];

__global__ void __launch_bounds__(256)
pack_wb_kernel(const float4* __restrict__ w4, const float4* __restrict__ b4)
{
    int i = blockIdx.x * blockDim.x + threadIdx.x;   // [0, TABLE_N/4)
    if (i >= TABLE_N / 4) return;
    float4 w = w4[i];
    float4 b = b4[i];
    float4* dst = reinterpret_cast<float4*>(&g_wb[4 * i]);
    dst[0] = make_float4(w.x, b.x, w.y, b.y);
    dst[1] = make_float4(w.z, b.z, w.w, b.w);
}

__device__ __forceinline__ unsigned part1by1(unsigned x) {
    x &= 0x0000ffffu;
    x = (x | (x << 8)) & 0x00FF00FFu;
    x = (x | (x << 4)) & 0x0F0F0F0Fu;
    x = (x | (x << 2)) & 0x33333333u;
    x = (x | (x << 1)) & 0x55555555u;
    return x;
}

// XLA-lowered index path: divide-by-constant == multiply by f32 reciprocal.
// All ops pinned to IEEE rn intrinsics; rintf == round-half-even; C cast ==
// truncate toward zero.
__device__ __forceinline__ int quad_index(float px, float py) {
    const float SCALE   = 10000000.0f;
    const float R_SCALE = 1.0f / 10000000.0f;
    const float R_W     = 1.0f / 360.0f;
    const float R_H     = 1.0f / 180.0f;
    float cx = __fmul_rn(rintf(__fmul_rn(px, SCALE)), R_SCALE);
    float cy = __fmul_rn(rintf(__fmul_rn(py, SCALE)), R_SCALE);
    float u  = __fmul_rn(__fadd_rn(cx, 180.0f), R_W);
    float v  = __fmul_rn(__fadd_rn(cy,  90.0f), R_H);
    int ix = (int)__fmul_rn(u, 512.0f);
    int iy = (int)__fmul_rn(v, 512.0f);
    ix = min(max(ix, 0), 511);
    iy = min(max(iy, 0), 511);
    return (int)(part1by1((unsigned)ix) | (part1by1((unsigned)iy) << 1));
}

// Persistent grid-stride kernel: 1184 CTAs loop over 2048-point tiles.
// Lane-contiguous strided layout inside a tile (point = tile*2048 + t + j*256)
// keeps all streaming traffic perfectly coalesced; the 8 gathers per thread
// per iteration are the only irregular L1 wavefronts. Cross-iteration
// scheduling lets iteration t+1's streaming loads overlap t's gathers.
__global__ void __launch_bounds__(NTHREADS)
quadpool_kernel(const float2* __restrict__ in2,  // [n]
                const float*  __restrict__ x,    // [n]
                float*        __restrict__ out,  // [n]
                int ntiles)
{
    for (int tile = blockIdx.x; tile < ntiles; tile += gridDim.x) {
        const int base = tile * CTA_PTS + threadIdx.x;

        // All streaming loads issued up front (evict-first: preserve L1 for
        // the gather table).
        float2 p[PPT];
#pragma unroll
        for (int j = 0; j < PPT; j++)
            p[j] = __ldcs(&in2[base + j * NTHREADS]);

        float xv[PPT];
#pragma unroll
        for (int j = 0; j < PPT; j++)
            xv[j] = __ldcs(&x[base + j * NTHREADS]);

        int idx[PPT];
#pragma unroll
        for (int j = 0; j < PPT; j++)
            idx[j] = quad_index(p[j].x, p[j].y);

        // 8 independent gathers in flight per thread.
        float2 wb[PPT];
#pragma unroll
        for (int j = 0; j < PPT; j++)
            wb[j] = __ldg(&g_wb[idx[j]]);

#pragma unroll
        for (int j = 0; j < PPT; j++)
            out[base + j * NTHREADS] = fmaf(wb[j].x, xv[j], wb[j].y);
    }
}

// Scalar tail for n % 2048 (not expected for N = 8388608, but safe).
__global__ void quadpool_tail_kernel(const float2* __restrict__ in2,
                                     const float*  __restrict__ x,
                                     float* __restrict__ out,
                                     int start, int n)
{
    int i = start + blockIdx.x * blockDim.x + threadIdx.x;
    if (i >= n) return;
    float2 pt = in2[i];
    float2 wb = __ldg(&g_wb[quad_index(pt.x, pt.y)]);
    out[i] = fmaf(wb.x, x[i], wb.y);
}

extern "C" void kernel_launch(void* const* d_in, const int* in_sizes, int n_in,
                              void* d_out, int out_size)
{
    const float* in  = (const float*)d_in[0];   // [N,2]
    const float* x   = (const float*)d_in[1];   // [N]
    const float* w   = (const float*)d_in[2];   // [262144]
    const float* b   = (const float*)d_in[3];   // [262144]
    float* out = (float*)d_out;

    pack_wb_kernel<<<TABLE_N / 4 / 256, 256>>>((const float4*)w, (const float4*)b);

    int n = in_sizes[1];
    int ntiles = n / CTA_PTS;
    if (ntiles > 0) {
        int grid = NSM * CTAS_PER_SM;          // 1184 persistent CTAs
        if (grid > ntiles) grid = ntiles;
        quadpool_kernel<<<grid, NTHREADS>>>((const float2*)in, x, out, ntiles);
    }
    int done = ntiles * CTA_PTS;
    int rem = n - done;
    if (rem > 0) {
        quadpool_tail_kernel<<<(rem + 255) / 256, 256>>>(
            (const float2*)in, x, out, done, n);
    }
}